// round 11
// baseline (speedup 1.0000x reference)
#include <cuda_runtime.h>
#include <cuda_bf16.h>
#include <cstdint>

#define N_ROWS 16384
#define DIM 128
#define SQRT_SCALE2 4.5398160f   // sqrt(log2(e)/0.07)
#define GRID 148
#define NUNITS 8256              // 128*129/2 upper-triangular block pairs

__device__ __nv_bfloat16 g_fn[N_ROWS * DIM];
__device__ float g_partial[GRID * N_ROWS];
__device__ float g_blocksum[512];
__device__ unsigned int g_ctr0;   // barrier: normalize -> gemm (monotonic)
__device__ unsigned int g_ctr2;   // lse last-block election    (monotonic)

#define TILE_BYTES 34816                 // 128 rows x 272B (136 bf16 padded)
#define SM_ROWACC  (4 * TILE_BYTES)      // 16384 floats (64KB)
#define SM_RED     (SM_ROWACC + 65536)   // 2 parities x 128x4 floats
#define SM_CRED    (SM_RED + 4096)       // 2 parities x 128x4 floats
#define SMEM_TOTAL (SM_CRED + 4096)      // 212992

__device__ __forceinline__ float fast_ex2(float x) {
    float y; asm("ex2.approx.ftz.f32 %0, %1;" : "=f"(y) : "f"(x)); return y;
}
__device__ __forceinline__ uint32_t smem_u32(const void* p) {
    uint32_t a;
    asm("{ .reg .u64 t; cvta.to.shared.u64 t, %1; cvt.u32.u64 %0, t; }" : "=r"(a) : "l"(p));
    return a;
}
__device__ __forceinline__ void cp16(uint32_t dst, const void* src) {
    asm volatile("cp.async.cg.shared.global [%0], [%1], 16;" :: "r"(dst), "l"(src));
}
__device__ __forceinline__ void cp_commit()   { asm volatile("cp.async.commit_group;"); }
__device__ __forceinline__ void cp_wait_all() { asm volatile("cp.async.wait_group 0;" ::: "memory"); }

__device__ __forceinline__ void ldsm4(uint32_t r[4], uint32_t addr) {
    asm volatile("ldmatrix.sync.aligned.m8n8.x4.shared.b16 {%0,%1,%2,%3}, [%4];"
                 : "=r"(r[0]), "=r"(r[1]), "=r"(r[2]), "=r"(r[3]) : "r"(addr));
}
__device__ __forceinline__ void mma16816(float* c, const uint32_t a[4], const uint32_t* b) {
    asm volatile(
      "mma.sync.aligned.m16n8k16.row.col.f32.bf16.bf16.f32 "
      "{%0,%1,%2,%3}, {%4,%5,%6,%7}, {%8,%9}, {%0,%1,%2,%3};\n"
      : "+f"(c[0]), "+f"(c[1]), "+f"(c[2]), "+f"(c[3])
      : "r"(a[0]), "r"(a[1]), "r"(a[2]), "r"(a[3]), "r"(b[0]), "r"(b[1]));
}

__device__ __forceinline__ int tri_base(int bi) { return bi * 128 - (bi * (bi - 1)) / 2; }
__device__ __forceinline__ void decode_unit(int u, int& bi, int& bj) {
    int b = (int)((257.0f - sqrtf(66049.0f - 8.0f * (float)u)) * 0.5f);
    while (tri_base(b + 1) <= u) b++;
    while (tri_base(b) > u) b--;
    bi = b;
    bj = b + (u - tri_base(b));
}

__device__ __forceinline__ void load_tile(uint32_t dstbase, const __nv_bfloat16* src, int tid) {
    #pragma unroll
    for (int i = 0; i < 4; i++) {
        int c = tid + 512 * i;
        int row = c >> 4, q = c & 15;
        cp16(dstbase + (uint32_t)(row * 17 + q) * 16, src + row * DIM + q * 8);
    }
}

// ---- MMA k-loop with interleaved ex2 epilogue of previous unit ----
// SINGLE instantiation per EPI value; pdiag is a runtime predicate so the
// unrolled body exists once (I$ footprint). ca always computed; discarded
// at flush time for diagonal units.
template<bool EPI>
__device__ __forceinline__ void kloop(uint32_t abase, uint32_t bbase, bool pdiag,
                                      float (&cc)[32], float (&cp)[32],
                                      float (&racc)[4], float (&ca)[8]) {
    const int lane = threadIdx.x & 31, warp = threadIdx.x >> 5;
    const int wm = warp >> 2, wn = warp & 3;
    const int g = lane >> 2, t = lane & 3;
    uint32_t aA0, aB0;
    {
        int rowA = lane & 15, koffA = (lane >> 4) * 16;
        aA0 = abase + (uint32_t)((wm * 32 + rowA) * 272 + koffA);
        int rowB = ((lane & 16) >> 1) + (lane & 7), koffB = ((lane >> 3) & 1) * 16;
        aB0 = bbase + (uint32_t)((wn * 32 + rowB) * 272 + koffB);
    }
    const int epi_r0 = wm * 32 + g, epi_c0 = wn * 32 + 2 * t;

    #pragma unroll
    for (int e = 0; e < 32; e++) cc[e] = 0.f;
    #pragma unroll
    for (int ks = 0; ks < 8; ks++) {
        uint32_t a0[4], a1[4], b0[4], b1[4];
        ldsm4(a0, aA0 + ks * 32);
        ldsm4(a1, aA0 + 16 * 272 + ks * 32);
        ldsm4(b0, aB0 + ks * 32);
        ldsm4(b1, aB0 + 16 * 272 + ks * 32);
        mma16816(&cc[0],  a0, b0 + 0); mma16816(&cc[4],  a0, b0 + 2);
        mma16816(&cc[8],  a0, b1 + 0); mma16816(&cc[12], a0, b1 + 2);
        mma16816(&cc[16], a1, b0 + 0); mma16816(&cc[20], a1, b0 + 2);
        mma16816(&cc[24], a1, b1 + 0); mma16816(&cc[28], a1, b1 + 2);
        if (EPI) {
            #pragma unroll
            for (int i = 0; i < 4; i++) {
                const int e = ks * 4 + i;
                const int mt = e >> 4, nt = (e >> 2) & 3, comp = e & 3;
                float ex = fast_ex2(cp[e]);
                int r  = epi_r0 + mt * 16 + (comp & 2) * 4;
                int cl = epi_c0 + nt * 8 + (comp & 1);
                if (pdiag && r == cl) ex = 1.f;        // masked diag: exp==1
                racc[mt * 2 + (comp >> 1)] += ex;
                ca[nt * 2 + (comp & 1)] += ex;
            }
        }
    }
}

__device__ __forceinline__ void flush_rows(unsigned char* smem_raw, float (&racc)[4], int wp) {
    const int lane = threadIdx.x & 31, warp = threadIdx.x >> 5;
    const int g = lane >> 2, t = lane & 3;
    const int wm = warp >> 2, wn = warp & 3;
    float rr[4];
    #pragma unroll
    for (int i = 0; i < 4; i++) {
        rr[i] = racc[i]; racc[i] = 0.f;
        rr[i] += __shfl_xor_sync(0xffffffffu, rr[i], 1);
        rr[i] += __shfl_xor_sync(0xffffffffu, rr[i], 2);
    }
    if (t == 0) {
        float* red = (float*)(smem_raw + SM_RED + wp * 2048);
        #pragma unroll
        for (int i = 0; i < 4; i++) {
            int r = wm * 32 + (i >> 1) * 16 + g + (i & 1) * 8;
            red[r * 4 + wn] = rr[i];
        }
    }
}

__device__ __forceinline__ void flush_cols(unsigned char* smem_raw, float (&ca)[8], int wp) {
    const int lane = threadIdx.x & 31, warp = threadIdx.x >> 5;
    const int t = lane & 3;
    const int wm = warp >> 2, wn = warp & 3;
    #pragma unroll
    for (int i = 0; i < 8; i++) {
        ca[i] += __shfl_xor_sync(0xffffffffu, ca[i], 4);
        ca[i] += __shfl_xor_sync(0xffffffffu, ca[i], 8);
        ca[i] += __shfl_xor_sync(0xffffffffu, ca[i], 16);
    }
    if (lane < 4) {
        float* cred = (float*)(smem_raw + SM_CRED + wp * 2048);
        #pragma unroll
        for (int i = 0; i < 8; i++) {
            int cl = wn * 32 + (i >> 1) * 8 + 2 * t + (i & 1);
            cred[cl * 4 + wm] = ca[i];
        }
    }
}

template<bool EPI>
__device__ __forceinline__ void do_step(uint32_t sbase, unsigned char* smem_raw, int tid,
                                        int abuf, int bbuf,
                                        bool has_next, bool loadA_next, int nbi, int nbj,
                                        bool pdiag, int wp, int lag_row, int lag_col,
                                        float (&cc)[32], float (&cp)[32], float (&racc)[4]) {
    cp_wait_all();
    __syncthreads();

    float* rowacc = (float*)(smem_raw + SM_ROWACC);
    if (tid < 128) {
        if (lag_row >= 0) {
            const float4* rp = (const float4*)(smem_raw + SM_RED + (wp ^ 1) * 2048);
            float4 v = rp[tid];
            rowacc[lag_row * 128 + tid] += (v.x + v.y) + (v.z + v.w);
        }
    } else if (tid < 256) {
        if (lag_col >= 0) {
            const float4* cq = (const float4*)(smem_raw + SM_CRED + (wp ^ 1) * 2048);
            float4 v = cq[tid - 128];
            rowacc[lag_col * 128 + (tid - 128)] += (v.x + v.y) + (v.z + v.w);
        }
    }

    if (has_next) {
        load_tile(sbase + (uint32_t)(2 + (bbuf ^ 1)) * TILE_BYTES,
                  g_fn + (size_t)nbj * 16384, tid);
        if (loadA_next)
            load_tile(sbase + (uint32_t)(abuf ^ 1) * TILE_BYTES,
                      g_fn + (size_t)nbi * 16384, tid);
        cp_commit();
    }

    const uint32_t abase = sbase + (uint32_t)abuf * TILE_BYTES;
    const uint32_t bbase = sbase + (uint32_t)(2 + bbuf) * TILE_BYTES;
    float ca[8] = {0.f, 0.f, 0.f, 0.f, 0.f, 0.f, 0.f, 0.f};
    kloop<EPI>(abase, bbase, pdiag, cc, cp, racc, ca);
    if (EPI && !pdiag) flush_cols(smem_raw, ca, wp);
}

__device__ __forceinline__ void tail_epi(unsigned char* smem_raw, float (&cp)[32],
                                         float (&racc)[4], bool pdiag, int wp) {
    const int lane = threadIdx.x & 31, warp = threadIdx.x >> 5;
    const int g = lane >> 2, t = lane & 3;
    const int wm = warp >> 2, wn = warp & 3;
    const int epi_r0 = wm * 32 + g, epi_c0 = wn * 32 + 2 * t;
    float ca[8] = {0.f, 0.f, 0.f, 0.f, 0.f, 0.f, 0.f, 0.f};
    #pragma unroll
    for (int e = 0; e < 32; e++) {
        const int mt = e >> 4, nt = (e >> 2) & 3, comp = e & 3;
        float ex = fast_ex2(cp[e]);
        int r  = epi_r0 + mt * 16 + (comp & 2) * 4;
        int cl = epi_c0 + nt * 8 + (comp & 1);
        if (pdiag && r == cl) ex = 1.f;
        racc[mt * 2 + (comp >> 1)] += ex;
        ca[nt * 2 + (comp & 1)] += ex;
    }
    flush_rows(smem_raw, racc, wp);
    if (!pdiag) flush_cols(smem_raw, ca, wp);
}

// ------- Kernel 1: normalize + grid barrier + symmetric GEMM/exp -------
__global__ void __launch_bounds__(512, 1) simclr_fused(const float* __restrict__ feats) {
    extern __shared__ unsigned char smem_raw[];
    const uint32_t sbase = smem_u32(smem_raw);
    const int tid = threadIdx.x;
    const int warp = tid >> 5, lane = tid & 31;
    const int c = blockIdx.x;

    // ---- phase 1: normalize + prescale (2 rows in flight per warp) ----
    {
        int base_row = 110 * c + min(c, 104);
        int cnt = (c < 104) ? 111 : 110;
        for (int r = warp * 2; r < cnt; r += 32) {
            int row0 = base_row + r;
            bool has2 = (r + 1 < cnt);
            int row1 = has2 ? (row0 + 1) : row0;
            float4 v0 = reinterpret_cast<const float4*>(feats + (size_t)row0 * DIM)[lane];
            float4 v1 = reinterpret_cast<const float4*>(feats + (size_t)row1 * DIM)[lane];
            float s0 = v0.x*v0.x + v0.y*v0.y + v0.z*v0.z + v0.w*v0.w;
            float s1 = v1.x*v1.x + v1.y*v1.y + v1.z*v1.z + v1.w*v1.w;
            #pragma unroll
            for (int o = 16; o; o >>= 1) {
                s0 += __shfl_xor_sync(0xffffffffu, s0, o);
                s1 += __shfl_xor_sync(0xffffffffu, s1, o);
            }
            float i0 = SQRT_SCALE2 / fmaxf(sqrtf(s0), 1e-8f);
            float i1 = SQRT_SCALE2 / fmaxf(sqrtf(s1), 1e-8f);
            __nv_bfloat162 p0 = __floats2bfloat162_rn(v0.x*i0, v0.y*i0);
            __nv_bfloat162 p1 = __floats2bfloat162_rn(v0.z*i0, v0.w*i0);
            uint2 w0;
            w0.x = *reinterpret_cast<uint32_t*>(&p0);
            w0.y = *reinterpret_cast<uint32_t*>(&p1);
            reinterpret_cast<uint2*>(g_fn + (size_t)row0 * DIM)[lane] = w0;
            if (has2) {
                __nv_bfloat162 q0 = __floats2bfloat162_rn(v1.x*i1, v1.y*i1);
                __nv_bfloat162 q1 = __floats2bfloat162_rn(v1.z*i1, v1.w*i1);
                uint2 w1;
                w1.x = *reinterpret_cast<uint32_t*>(&q0);
                w1.y = *reinterpret_cast<uint32_t*>(&q1);
                reinterpret_cast<uint2*>(g_fn + (size_t)row1 * DIM)[lane] = w1;
            }
        }
    }
    #pragma unroll
    for (int i = 0; i < 8; i++)
        reinterpret_cast<float4*>(smem_raw + SM_ROWACC)[tid + 512 * i] =
            make_float4(0.f, 0.f, 0.f, 0.f);

    // grid barrier (monotonic counter — safe across graph replays)
    __threadfence();
    __syncthreads();
    if (tid == 0) {
        unsigned int old = atomicAdd(&g_ctr0, 1u);
        unsigned int target = old - (old % GRID) + GRID;
        while (atomicAdd(&g_ctr0, 0u) < target) __nanosleep(64);
    }
    __syncthreads();

    // ---- phase 2: unit loop (contiguous row-major triangular walk) ----
    const int u0 = 55 * c + min(c, 116);
    const int count = (c < 116) ? 56 : 55;

    int bi, bj;
    decode_unit(u0, bi, bj);
    int abuf = 0, bbuf = 0;
    load_tile(sbase, g_fn + (size_t)bi * 16384, tid);
    load_tile(sbase + 2 * TILE_BYTES, g_fn + (size_t)bj * 16384, tid);
    cp_commit();

    float cA[32], cB[32], racc[4] = {0.f, 0.f, 0.f, 0.f};

    int nbi = bi, nbj = bj + 1;
    if (nbj == 128) { nbi = bi + 1; nbj = nbi; }
    bool has_next = (count > 1);
    bool loadA = has_next && (nbi != bi);
    do_step<false>(sbase, smem_raw, tid, abuf, bbuf, has_next, loadA, nbi, nbj,
                   false, 0, -1, -1, cA, cB, racc);
    int pbi = bi, pbj = bj;
    bool pdiag = (bi == bj);
    bbuf ^= 1; if (loadA) abuf ^= 1;
    bi = nbi; bj = nbj;

    int lag_row = -1, lag_col = -1;
    int wp = 1;
    #pragma unroll 1
    for (int s = 1; s < count; s++) {
        nbj = bj + 1; nbi = bi;
        if (nbj == 128) { nbi = bi + 1; nbj = nbi; }
        has_next = (s + 1 < count);
        loadA = has_next && (nbi != bi);
        const bool rowflush = (bi != pbi);

        if (s & 1) do_step<true>(sbase, smem_raw, tid, abuf, bbuf, has_next, loadA,
                                 nbi, nbj, pdiag, wp, lag_row, lag_col, cB, cA, racc);
        else       do_step<true>(sbase, smem_raw, tid, abuf, bbuf, has_next, loadA,
                                 nbi, nbj, pdiag, wp, lag_row, lag_col, cA, cB, racc);
        if (rowflush) flush_rows(smem_raw, racc, wp);
        lag_row = rowflush ? pbi : -1;
        lag_col = pdiag ? -1 : pbj;
        pbi = bi; pbj = bj; pdiag = (bi == bj);
        bbuf ^= 1; if (loadA) abuf ^= 1;
        bi = nbi; bj = nbj;
        wp ^= 1;
    }

    // ---- tail ----
    __syncthreads();
    {
        float* rowacc = (float*)(smem_raw + SM_ROWACC);
        if (tid < 128 && lag_row >= 0) {
            const float4* rp = (const float4*)(smem_raw + SM_RED + (wp ^ 1) * 2048);
            float4 v = rp[tid];
            rowacc[lag_row * 128 + tid] += (v.x + v.y) + (v.z + v.w);
        } else if (tid >= 128 && tid < 256 && lag_col >= 0) {
            const float4* cq = (const float4*)(smem_raw + SM_CRED + (wp ^ 1) * 2048);
            float4 v = cq[tid - 128];
            rowacc[lag_col * 128 + (tid - 128)] += (v.x + v.y) + (v.z + v.w);
        }
    }
    if ((count - 1) & 1) tail_epi(smem_raw, cB, racc, pdiag, wp);
    else                 tail_epi(smem_raw, cA, racc, pdiag, wp);
    __syncthreads();
    {
        float* rowacc = (float*)(smem_raw + SM_ROWACC);
        if (tid < 128) {
            const float4* rp = (const float4*)(smem_raw + SM_RED + wp * 2048);
            float4 v = rp[tid];
            rowacc[pbi * 128 + tid] += (v.x + v.y) + (v.z + v.w);
        } else if (tid < 256 && !pdiag) {
            const float4* cq = (const float4*)(smem_raw + SM_CRED + wp * 2048);
            float4 v = cq[tid - 128];
            rowacc[pbj * 128 + (tid - 128)] += (v.x + v.y) + (v.z + v.w);
        }
    }
    __syncthreads();
    float* dst = g_partial + (size_t)c * N_ROWS;
    #pragma unroll
    for (int i = 0; i < 8; i++) {
        int idx = tid + 512 * i;
        reinterpret_cast<float4*>(dst)[idx] =
            reinterpret_cast<const float4*>(smem_raw + SM_ROWACC)[idx];
    }
}

// ------- Kernel 2: row sums + log + fused final mean -------
// 512 blocks x 256 threads; block owns 32 rows; 8-way split of the 148
// partials (8x19 with guard). Warp-coalesced ldcg over L2-resident data.
__global__ void __launch_bounds__(256) lse_final(float* __restrict__ out) {
    __shared__ float s[256];
    __shared__ float w2[8];
    __shared__ int amLast;
    const int tid = threadIdx.x;
    const int row = blockIdx.x * 32 + (tid & 31);
    const int q = tid >> 5;                 // 0..7
    float acc = 0.f;
    #pragma unroll
    for (int k = 0; k < 19; k++) {
        int c = q * 19 + k;
        if (c < GRID) acc += __ldcg(&g_partial[(size_t)c * N_ROWS + row]);
    }
    s[tid] = acc;
    __syncthreads();
    if (tid < 32) {
        float v = 0.f;
        #pragma unroll
        for (int j = 0; j < 8; j++) v += s[tid + 32 * j];
        float l = logf(v);
        #pragma unroll
        for (int o = 16; o; o >>= 1) l += __shfl_xor_sync(0xffffffffu, l, o);
        if (tid == 0) g_blocksum[blockIdx.x] = l;
    }
    __threadfence();
    if (tid == 0) {
        unsigned int t2 = atomicAdd(&g_ctr2, 1u);
        amLast = ((t2 % 512u) == 511u) ? 1 : 0;
    }
    __syncthreads();
    if (amLast) {
        float v = __ldcg(&g_blocksum[tid]) + __ldcg(&g_blocksum[tid + 256]);
        #pragma unroll
        for (int o = 16; o; o >>= 1) v += __shfl_xor_sync(0xffffffffu, v, o);
        if ((tid & 31) == 0) w2[tid >> 5] = v;
        __syncthreads();
        if (tid == 0) {
            float tot = 0.f;
            #pragma unroll
            for (int i = 0; i < 8; i++) tot += w2[i];
            out[0] = tot * (1.0f / 16384.0f) - 1.2857142857142857e-13f;
        }
    }
}

extern "C" void kernel_launch(void* const* d_in, const int* in_sizes, int n_in,
                              void* d_out, int out_size) {
    const float* feats = (const float*)d_in[0];
    float* out = (float*)d_out;

    cudaFuncSetAttribute(simclr_fused,
                         cudaFuncAttributeMaxDynamicSharedMemorySize, SMEM_TOTAL);

    simclr_fused<<<GRID, 512, SMEM_TOTAL>>>(feats);
    lse_final<<<512, 256>>>(out);
}

// round 12
// speedup vs baseline: 1.0234x; 1.0234x over previous
#include <cuda_runtime.h>
#include <cuda_bf16.h>
#include <cstdint>

#define N_ROWS 16384
#define DIM 128
#define SQRT_SCALE2 4.5398160f   // sqrt(log2(e)/0.07)
#define GRID 148
#define NUNITS 8256              // 128*129/2 upper-triangular block pairs

__device__ __nv_bfloat16 g_fn[N_ROWS * DIM];
__device__ float g_partial[GRID * N_ROWS];
__device__ float g_blocksum[256];
__device__ unsigned int g_ctr0;   // barrier: normalize -> gemm (monotonic)
__device__ unsigned int g_ctr2;   // lse last-block election    (monotonic)

#define TILE_BYTES 34816                 // 128 rows x 272B (136 bf16 padded)
#define SM_ROWACC  (4 * TILE_BYTES)      // 16384 floats (64KB)
#define SM_RED     (SM_ROWACC + 65536)   // 2 parities x 128x4 floats
#define SM_CRED    (SM_RED + 4096)       // 2 parities x 128x4 floats
#define SMEM_TOTAL (SM_CRED + 4096)      // 212992

__device__ __forceinline__ float fast_ex2(float x) {
    float y; asm("ex2.approx.ftz.f32 %0, %1;" : "=f"(y) : "f"(x)); return y;
}
__device__ __forceinline__ uint32_t smem_u32(const void* p) {
    uint32_t a;
    asm("{ .reg .u64 t; cvta.to.shared.u64 t, %1; cvt.u32.u64 %0, t; }" : "=r"(a) : "l"(p));
    return a;
}
__device__ __forceinline__ void cp16(uint32_t dst, const void* src) {
    asm volatile("cp.async.cg.shared.global [%0], [%1], 16;" :: "r"(dst), "l"(src));
}
__device__ __forceinline__ void cp_commit()   { asm volatile("cp.async.commit_group;"); }
__device__ __forceinline__ void cp_wait_all() { asm volatile("cp.async.wait_group 0;" ::: "memory"); }

__device__ __forceinline__ void ldsm4(uint32_t r[4], uint32_t addr) {
    asm volatile("ldmatrix.sync.aligned.m8n8.x4.shared.b16 {%0,%1,%2,%3}, [%4];"
                 : "=r"(r[0]), "=r"(r[1]), "=r"(r[2]), "=r"(r[3]) : "r"(addr));
}
__device__ __forceinline__ void mma16816(float* c, const uint32_t a[4], const uint32_t* b) {
    asm volatile(
      "mma.sync.aligned.m16n8k16.row.col.f32.bf16.bf16.f32 "
      "{%0,%1,%2,%3}, {%4,%5,%6,%7}, {%8,%9}, {%0,%1,%2,%3};\n"
      : "+f"(c[0]), "+f"(c[1]), "+f"(c[2]), "+f"(c[3])
      : "r"(a[0]), "r"(a[1]), "r"(a[2]), "r"(a[3]), "r"(b[0]), "r"(b[1]));
}

__device__ __forceinline__ int tri_base(int bi) { return bi * 128 - (bi * (bi - 1)) / 2; }
__device__ __forceinline__ void decode_unit(int u, int& bi, int& bj) {
    int b = (int)((257.0f - sqrtf(66049.0f - 8.0f * (float)u)) * 0.5f);
    while (tri_base(b + 1) <= u) b++;
    while (tri_base(b) > u) b--;
    bi = b;
    bj = b + (u - tri_base(b));
}

__device__ __forceinline__ void load_tile(uint32_t dstbase, const __nv_bfloat16* src, int tid) {
    #pragma unroll
    for (int i = 0; i < 4; i++) {
        int c = tid + 512 * i;
        int row = c >> 4, q = c & 15;
        cp16(dstbase + (uint32_t)(row * 17 + q) * 16, src + row * DIM + q * 8);
    }
}

// Zero the diagonal elements of a freshly computed diagonal-unit tile so the
// downstream exp epilogue yields exactly 1.0 (= exp(9e-15/T)). Runs for ~1
// unit per CTA — keeps the hot epilogue compare-free.
__device__ __forceinline__ void patch_diag(float (&cc)[32]) {
    const int lane = threadIdx.x & 31, warp = threadIdx.x >> 5;
    const int wm = warp >> 2, wn = warp & 3;
    const int g = lane >> 2, t = lane & 3;
    const int d = (wm * 32 + g) - (wn * 32 + 2 * t);   // epi_r0 - epi_c0
    #pragma unroll
    for (int e = 0; e < 32; e++) {
        const int mt = e >> 4, nt = (e >> 2) & 3, comp = e & 3;
        const int delta = (nt * 8 + (comp & 1)) - (mt * 16 + (comp & 2) * 4);
        if (d == delta) cc[e] = 0.f;
    }
}

// ---- MMA k-loop with interleaved, compare-free ex2 epilogue ----
template<bool EPI>
__device__ __forceinline__ void kloop(uint32_t abase, uint32_t bbase,
                                      float (&cc)[32], float (&cp)[32],
                                      float (&racc)[4], float (&ca)[8]) {
    const int lane = threadIdx.x & 31, warp = threadIdx.x >> 5;
    const int wm = warp >> 2, wn = warp & 3;
    uint32_t aA0, aB0;
    {
        int rowA = lane & 15, koffA = (lane >> 4) * 16;
        aA0 = abase + (uint32_t)((wm * 32 + rowA) * 272 + koffA);
        int rowB = ((lane & 16) >> 1) + (lane & 7), koffB = ((lane >> 3) & 1) * 16;
        aB0 = bbase + (uint32_t)((wn * 32 + rowB) * 272 + koffB);
    }

    #pragma unroll
    for (int e = 0; e < 32; e++) cc[e] = 0.f;
    #pragma unroll
    for (int ks = 0; ks < 8; ks++) {
        uint32_t a0[4], a1[4], b0[4], b1[4];
        ldsm4(a0, aA0 + ks * 32);
        ldsm4(a1, aA0 + 16 * 272 + ks * 32);
        ldsm4(b0, aB0 + ks * 32);
        ldsm4(b1, aB0 + 16 * 272 + ks * 32);
        mma16816(&cc[0],  a0, b0 + 0); mma16816(&cc[4],  a0, b0 + 2);
        mma16816(&cc[8],  a0, b1 + 0); mma16816(&cc[12], a0, b1 + 2);
        mma16816(&cc[16], a1, b0 + 0); mma16816(&cc[20], a1, b0 + 2);
        mma16816(&cc[24], a1, b1 + 0); mma16816(&cc[28], a1, b1 + 2);
        if (EPI) {
            #pragma unroll
            for (int i = 0; i < 4; i++) {
                const int e = ks * 4 + i;
                const int mt = e >> 4, nt = (e >> 2) & 3, comp = e & 3;
                float ex = fast_ex2(cp[e]);
                racc[mt * 2 + (comp >> 1)] += ex;
                ca[nt * 2 + (comp & 1)] += ex;
            }
        }
    }
}

__device__ __forceinline__ void flush_rows(unsigned char* smem_raw, float (&racc)[4], int wp) {
    const int lane = threadIdx.x & 31, warp = threadIdx.x >> 5;
    const int g = lane >> 2, t = lane & 3;
    const int wm = warp >> 2, wn = warp & 3;
    float rr[4];
    #pragma unroll
    for (int i = 0; i < 4; i++) {
        rr[i] = racc[i]; racc[i] = 0.f;
        rr[i] += __shfl_xor_sync(0xffffffffu, rr[i], 1);
        rr[i] += __shfl_xor_sync(0xffffffffu, rr[i], 2);
    }
    if (t == 0) {
        float* red = (float*)(smem_raw + SM_RED + wp * 2048);
        #pragma unroll
        for (int i = 0; i < 4; i++) {
            int r = wm * 32 + (i >> 1) * 16 + g + (i & 1) * 8;
            red[r * 4 + wn] = rr[i];
        }
    }
}

__device__ __forceinline__ void flush_cols(unsigned char* smem_raw, float (&ca)[8], int wp) {
    const int lane = threadIdx.x & 31, warp = threadIdx.x >> 5;
    const int t = lane & 3;
    const int wm = warp >> 2, wn = warp & 3;
    #pragma unroll
    for (int i = 0; i < 8; i++) {
        ca[i] += __shfl_xor_sync(0xffffffffu, ca[i], 4);
        ca[i] += __shfl_xor_sync(0xffffffffu, ca[i], 8);
        ca[i] += __shfl_xor_sync(0xffffffffu, ca[i], 16);
    }
    if (lane < 4) {
        float* cred = (float*)(smem_raw + SM_CRED + wp * 2048);
        #pragma unroll
        for (int i = 0; i < 8; i++) {
            int cl = wn * 32 + (i >> 1) * 8 + 2 * t + (i & 1);
            cred[cl * 4 + wm] = ca[i];
        }
    }
}

// One pipeline step. cur_diag: this unit is a diagonal tile (patch cc after MMA).
// pdiag: the PREVIOUS unit (being exp'd here) was diagonal (skip its col flush).
template<bool EPI>
__device__ __forceinline__ void do_step(uint32_t sbase, unsigned char* smem_raw, int tid,
                                        int abuf, int bbuf,
                                        bool has_next, bool loadA_next, int nbi, int nbj,
                                        bool cur_diag, bool pdiag, int wp,
                                        int lag_row, int lag_col,
                                        float (&cc)[32], float (&cp)[32], float (&racc)[4]) {
    cp_wait_all();
    __syncthreads();

    float* rowacc = (float*)(smem_raw + SM_ROWACC);
    if (tid < 128) {
        if (lag_row >= 0) {
            const float4* rp = (const float4*)(smem_raw + SM_RED + (wp ^ 1) * 2048);
            float4 v = rp[tid];
            rowacc[lag_row * 128 + tid] += (v.x + v.y) + (v.z + v.w);
        }
    } else if (tid < 256) {
        if (lag_col >= 0) {
            const float4* cq = (const float4*)(smem_raw + SM_CRED + (wp ^ 1) * 2048);
            float4 v = cq[tid - 128];
            rowacc[lag_col * 128 + (tid - 128)] += (v.x + v.y) + (v.z + v.w);
        }
    }

    if (has_next) {
        load_tile(sbase + (uint32_t)(2 + (bbuf ^ 1)) * TILE_BYTES,
                  g_fn + (size_t)nbj * 16384, tid);
        if (loadA_next)
            load_tile(sbase + (uint32_t)(abuf ^ 1) * TILE_BYTES,
                      g_fn + (size_t)nbi * 16384, tid);
        cp_commit();
    }

    const uint32_t abase = sbase + (uint32_t)abuf * TILE_BYTES;
    const uint32_t bbase = sbase + (uint32_t)(2 + bbuf) * TILE_BYTES;
    float ca[8] = {0.f, 0.f, 0.f, 0.f, 0.f, 0.f, 0.f, 0.f};
    kloop<EPI>(abase, bbase, cc, cp, racc, ca);
    if (cur_diag) patch_diag(cc);              // rare; zero diag -> exp==1 later
    if (EPI && !pdiag) flush_cols(smem_raw, ca, wp);
}

__device__ __forceinline__ void tail_epi(unsigned char* smem_raw, float (&cp)[32],
                                         float (&racc)[4], bool pdiag, int wp) {
    float ca[8] = {0.f, 0.f, 0.f, 0.f, 0.f, 0.f, 0.f, 0.f};
    #pragma unroll
    for (int e = 0; e < 32; e++) {
        const int mt = e >> 4, nt = (e >> 2) & 3, comp = e & 3;
        float ex = fast_ex2(cp[e]);           // cc pre-patched for diag units
        racc[mt * 2 + (comp >> 1)] += ex;
        ca[nt * 2 + (comp & 1)] += ex;
    }
    flush_rows(smem_raw, racc, wp);
    if (!pdiag) flush_cols(smem_raw, ca, wp);
}

// ------- Kernel 1: normalize + grid barrier + symmetric GEMM/exp -------
__global__ void __launch_bounds__(512, 1) simclr_fused(const float* __restrict__ feats) {
    extern __shared__ unsigned char smem_raw[];
    const uint32_t sbase = smem_u32(smem_raw);
    const int tid = threadIdx.x;
    const int warp = tid >> 5, lane = tid & 31;
    const int c = blockIdx.x;

    // ---- phase 1: normalize + prescale (2 rows in flight per warp) ----
    {
        int base_row = 110 * c + min(c, 104);
        int cnt = (c < 104) ? 111 : 110;
        for (int r = warp * 2; r < cnt; r += 32) {
            int row0 = base_row + r;
            bool has2 = (r + 1 < cnt);
            int row1 = has2 ? (row0 + 1) : row0;
            float4 v0 = reinterpret_cast<const float4*>(feats + (size_t)row0 * DIM)[lane];
            float4 v1 = reinterpret_cast<const float4*>(feats + (size_t)row1 * DIM)[lane];
            float s0 = v0.x*v0.x + v0.y*v0.y + v0.z*v0.z + v0.w*v0.w;
            float s1 = v1.x*v1.x + v1.y*v1.y + v1.z*v1.z + v1.w*v1.w;
            #pragma unroll
            for (int o = 16; o; o >>= 1) {
                s0 += __shfl_xor_sync(0xffffffffu, s0, o);
                s1 += __shfl_xor_sync(0xffffffffu, s1, o);
            }
            float i0 = SQRT_SCALE2 / fmaxf(sqrtf(s0), 1e-8f);
            float i1 = SQRT_SCALE2 / fmaxf(sqrtf(s1), 1e-8f);
            __nv_bfloat162 p0 = __floats2bfloat162_rn(v0.x*i0, v0.y*i0);
            __nv_bfloat162 p1 = __floats2bfloat162_rn(v0.z*i0, v0.w*i0);
            uint2 w0;
            w0.x = *reinterpret_cast<uint32_t*>(&p0);
            w0.y = *reinterpret_cast<uint32_t*>(&p1);
            reinterpret_cast<uint2*>(g_fn + (size_t)row0 * DIM)[lane] = w0;
            if (has2) {
                __nv_bfloat162 q0 = __floats2bfloat162_rn(v1.x*i1, v1.y*i1);
                __nv_bfloat162 q1 = __floats2bfloat162_rn(v1.z*i1, v1.w*i1);
                uint2 w1;
                w1.x = *reinterpret_cast<uint32_t*>(&q0);
                w1.y = *reinterpret_cast<uint32_t*>(&q1);
                reinterpret_cast<uint2*>(g_fn + (size_t)row1 * DIM)[lane] = w1;
            }
        }
    }
    #pragma unroll
    for (int i = 0; i < 8; i++)
        reinterpret_cast<float4*>(smem_raw + SM_ROWACC)[tid + 512 * i] =
            make_float4(0.f, 0.f, 0.f, 0.f);

    // grid barrier (monotonic counter — safe across graph replays)
    __threadfence();
    __syncthreads();
    if (tid == 0) {
        unsigned int old = atomicAdd(&g_ctr0, 1u);
        unsigned int target = old - (old % GRID) + GRID;
        while (atomicAdd(&g_ctr0, 0u) < target) __nanosleep(64);
    }
    __syncthreads();

    // ---- phase 2: unit loop (contiguous row-major triangular walk) ----
    const int u0 = 55 * c + min(c, 116);
    const int count = (c < 116) ? 56 : 55;

    int bi, bj;
    decode_unit(u0, bi, bj);
    int abuf = 0, bbuf = 0;
    load_tile(sbase, g_fn + (size_t)bi * 16384, tid);
    load_tile(sbase + 2 * TILE_BYTES, g_fn + (size_t)bj * 16384, tid);
    cp_commit();

    float cA[32], cB[32], racc[4] = {0.f, 0.f, 0.f, 0.f};

    int nbi = bi, nbj = bj + 1;
    if (nbj == 128) { nbi = bi + 1; nbj = nbi; }
    bool has_next = (count > 1);
    bool loadA = has_next && (nbi != bi);
    do_step<false>(sbase, smem_raw, tid, abuf, bbuf, has_next, loadA, nbi, nbj,
                   bi == bj, false, 0, -1, -1, cA, cB, racc);
    int pbi = bi, pbj = bj;
    bool pdiag = (bi == bj);
    bbuf ^= 1; if (loadA) abuf ^= 1;
    bi = nbi; bj = nbj;

    int lag_row = -1, lag_col = -1;
    int wp = 1;
    #pragma unroll 1
    for (int s = 1; s < count; s++) {
        nbj = bj + 1; nbi = bi;
        if (nbj == 128) { nbi = bi + 1; nbj = nbi; }
        has_next = (s + 1 < count);
        loadA = has_next && (nbi != bi);
        const bool rowflush = (bi != pbi);
        const bool cdiag = (bi == bj);

        if (s & 1) do_step<true>(sbase, smem_raw, tid, abuf, bbuf, has_next, loadA,
                                 nbi, nbj, cdiag, pdiag, wp, lag_row, lag_col, cB, cA, racc);
        else       do_step<true>(sbase, smem_raw, tid, abuf, bbuf, has_next, loadA,
                                 nbi, nbj, cdiag, pdiag, wp, lag_row, lag_col, cA, cB, racc);
        if (rowflush) flush_rows(smem_raw, racc, wp);
        lag_row = rowflush ? pbi : -1;
        lag_col = pdiag ? -1 : pbj;
        pbi = bi; pbj = bj; pdiag = cdiag;
        bbuf ^= 1; if (loadA) abuf ^= 1;
        bi = nbi; bj = nbj;
        wp ^= 1;
    }

    // ---- tail ----
    __syncthreads();
    {
        float* rowacc = (float*)(smem_raw + SM_ROWACC);
        if (tid < 128 && lag_row >= 0) {
            const float4* rp = (const float4*)(smem_raw + SM_RED + (wp ^ 1) * 2048);
            float4 v = rp[tid];
            rowacc[lag_row * 128 + tid] += (v.x + v.y) + (v.z + v.w);
        } else if (tid >= 128 && tid < 256 && lag_col >= 0) {
            const float4* cq = (const float4*)(smem_raw + SM_CRED + (wp ^ 1) * 2048);
            float4 v = cq[tid - 128];
            rowacc[lag_col * 128 + (tid - 128)] += (v.x + v.y) + (v.z + v.w);
        }
    }
    if ((count - 1) & 1) tail_epi(smem_raw, cB, racc, pdiag, wp);
    else                 tail_epi(smem_raw, cA, racc, pdiag, wp);
    __syncthreads();
    {
        float* rowacc = (float*)(smem_raw + SM_ROWACC);
        if (tid < 128) {
            const float4* rp = (const float4*)(smem_raw + SM_RED + wp * 2048);
            float4 v = rp[tid];
            rowacc[pbi * 128 + tid] += (v.x + v.y) + (v.z + v.w);
        } else if (tid < 256 && !pdiag) {
            const float4* cq = (const float4*)(smem_raw + SM_CRED + wp * 2048);
            float4 v = cq[tid - 128];
            rowacc[pbj * 128 + (tid - 128)] += (v.x + v.y) + (v.z + v.w);
        }
    }
    __syncthreads();
    float* dst = g_partial + (size_t)c * N_ROWS;
    #pragma unroll
    for (int i = 0; i < 8; i++) {
        int idx = tid + 512 * i;
        reinterpret_cast<float4*>(dst)[idx] =
            reinterpret_cast<const float4*>(smem_raw + SM_ROWACC)[idx];
    }
}

// ------- Kernel 2: row sums + log + fused final mean (R7-measured-best) -------
__global__ void __launch_bounds__(256) lse_final(float* __restrict__ out) {
    __shared__ float s[256];
    __shared__ int amLast;
    const int tid = threadIdx.x;
    const int row = blockIdx.x * 64 + (tid & 63);
    const int cbeg = (tid >> 6) * 37;
    float acc = 0.f;
    #pragma unroll
    for (int k = 0; k < 37; k++)
        acc += __ldcg(&g_partial[(size_t)(cbeg + k) * N_ROWS + row]);
    s[tid] = acc;
    __syncthreads();
    if (tid < 64) {
        float v = (s[tid] + s[tid + 64]) + (s[tid + 128] + s[tid + 192]);
        float l = logf(v);
        #pragma unroll
        for (int o = 16; o; o >>= 1) l += __shfl_xor_sync(0xffffffffu, l, o);
        if ((tid & 31) == 0) s[tid >> 5] = l;
    }
    __syncthreads();
    if (tid == 0) g_blocksum[blockIdx.x] = s[0] + s[1];
    __threadfence();
    if (tid == 0) {
        unsigned int t2 = atomicAdd(&g_ctr2, 1u);
        amLast = ((t2 % 256u) == 255u) ? 1 : 0;
    }
    __syncthreads();
    if (amLast) {
        const volatile float* bs = g_blocksum;
        float v = bs[tid];
        #pragma unroll
        for (int o = 16; o; o >>= 1) v += __shfl_xor_sync(0xffffffffu, v, o);
        if ((tid & 31) == 0) s[tid >> 5] = v;
        __syncthreads();
        if (tid == 0) {
            float tot = 0.f;
            #pragma unroll
            for (int i = 0; i < 8; i++) tot += s[i];
            out[0] = tot * (1.0f / 16384.0f) - 1.2857142857142857e-13f;
        }
    }
}

extern "C" void kernel_launch(void* const* d_in, const int* in_sizes, int n_in,
                              void* d_out, int out_size) {
    const float* feats = (const float*)d_in[0];
    float* out = (float*)d_out;

    cudaFuncSetAttribute(simclr_fused,
                         cudaFuncAttributeMaxDynamicSharedMemorySize, SMEM_TOTAL);

    simclr_fused<<<GRID, 512, SMEM_TOTAL>>>(feats);
    lse_final<<<256, 256>>>(out);
}